// round 1
// baseline (speedup 1.0000x reference)
#include <cuda_runtime.h>
#include <math.h>

#define Bsz 2
#define Lsz 2048
#define Esz 1024
#define Hsz 16
#define Dsz 64
#define NROW (Bsz*Lsz)          // 4096
#define BLE  (Bsz*Lsz*Esz)      // 4,194,304 elements (16MB fp32)

// scratch: qr qi kr ki vr vi or oi  (8 x 16MB = 128MB)
__device__ float g_scratch[8u * BLE];

// ---------------------------------------------------------------------------
// Fused complex GEMM:  Y = X @ W^T + b   (complex), X:[4096,1024] W:[1024,1024]
//   Yr = Xr Wr^T - Xi Wi^T + br ;  Yi = Xr Wi^T + Xi Wr^T + bi
// ---------------------------------------------------------------------------
#define BM 64
#define BN 64
#define BK 16

__global__ __launch_bounds__(256) void cgemm_kernel(
    const float* __restrict__ Xr, const float* __restrict__ Xi,
    const float* __restrict__ Wr, const float* __restrict__ Wi,
    const float* __restrict__ br, const float* __restrict__ bi,
    float* __restrict__ Yr, float* __restrict__ Yi)
{
    __shared__ float sXr[BK][BM];
    __shared__ float sXi[BK][BM];
    __shared__ float sWr[BK][BN];
    __shared__ float sWi[BK][BN];

    const int tid = threadIdx.x;
    const int tx = tid & 15;          // n micro-tile
    const int ty = tid >> 4;          // m micro-tile
    const int m0 = blockIdx.y * BM;
    const int n0 = blockIdx.x * BN;

    // loader mapping: each thread loads one float4 per matrix per k-tile
    const int lrow = tid >> 2;        // 0..63
    const int lk   = (tid & 3) << 2;  // 0,4,8,12

    const float* pXr = Xr + (size_t)(m0 + lrow) * Esz + lk;
    const float* pXi = Xi + (size_t)(m0 + lrow) * Esz + lk;
    const float* pWr = Wr + (size_t)(n0 + lrow) * Esz + lk;
    const float* pWi = Wi + (size_t)(n0 + lrow) * Esz + lk;

    float accR[4][4] = {};
    float accI[4][4] = {};

    for (int kt = 0; kt < Esz; kt += BK) {
        float4 xr = *(const float4*)(pXr + kt);
        float4 xi = *(const float4*)(pXi + kt);
        float4 wr = *(const float4*)(pWr + kt);
        float4 wi = *(const float4*)(pWi + kt);
        __syncthreads();
        sXr[lk+0][lrow] = xr.x; sXr[lk+1][lrow] = xr.y; sXr[lk+2][lrow] = xr.z; sXr[lk+3][lrow] = xr.w;
        sXi[lk+0][lrow] = xi.x; sXi[lk+1][lrow] = xi.y; sXi[lk+2][lrow] = xi.z; sXi[lk+3][lrow] = xi.w;
        sWr[lk+0][lrow] = wr.x; sWr[lk+1][lrow] = wr.y; sWr[lk+2][lrow] = wr.z; sWr[lk+3][lrow] = wr.w;
        sWi[lk+0][lrow] = wi.x; sWi[lk+1][lrow] = wi.y; sWi[lk+2][lrow] = wi.z; sWi[lk+3][lrow] = wi.w;
        __syncthreads();
        #pragma unroll
        for (int k = 0; k < BK; ++k) {
            float4 a4 = *(const float4*)&sXr[k][ty << 2];
            float4 c4 = *(const float4*)&sXi[k][ty << 2];
            float4 u4 = *(const float4*)&sWr[k][tx << 2];
            float4 v4 = *(const float4*)&sWi[k][tx << 2];
            float ar[4] = {a4.x, a4.y, a4.z, a4.w};
            float ai[4] = {c4.x, c4.y, c4.z, c4.w};
            float ur[4] = {u4.x, u4.y, u4.z, u4.w};
            float ui[4] = {v4.x, v4.y, v4.z, v4.w};
            #pragma unroll
            for (int i = 0; i < 4; ++i) {
                #pragma unroll
                for (int j = 0; j < 4; ++j) {
                    accR[i][j] = fmaf(ar[i], ur[j], accR[i][j]);
                    accR[i][j] = fmaf(-ai[i], ui[j], accR[i][j]);
                    accI[i][j] = fmaf(ar[i], ui[j], accI[i][j]);
                    accI[i][j] = fmaf(ai[i], ur[j], accI[i][j]);
                }
            }
        }
    }

    const int nn = n0 + (tx << 2);
    float bR[4], bI[4];
    #pragma unroll
    for (int j = 0; j < 4; ++j) { bR[j] = br[nn + j]; bI[j] = bi[nn + j]; }
    #pragma unroll
    for (int i = 0; i < 4; ++i) {
        size_t row = (size_t)(m0 + (ty << 2) + i) * Esz + nn;
        float4 yr = make_float4(accR[i][0] + bR[0], accR[i][1] + bR[1],
                                accR[i][2] + bR[2], accR[i][3] + bR[3]);
        float4 yi = make_float4(accI[i][0] + bI[0], accI[i][1] + bI[1],
                                accI[i][2] + bI[2], accI[i][3] + bI[3]);
        *(float4*)&Yr[row] = yr;
        *(float4*)&Yi[row] = yi;
    }
}

// ---------------------------------------------------------------------------
// Flash attention:  S = (Qr Kr^T + Qi Ki^T)/sqrt(D),  P = softmax(S),
//                   Or = P Vr, Oi = P Vi.   One block per (b,h, 64-q-tile).
// ---------------------------------------------------------------------------
#define SP 68   // padded stride for 64-wide shared tiles

__device__ __forceinline__ float fexp2(float x) {
    float y;
    asm("ex2.approx.ftz.f32 %0, %1;" : "=f"(y) : "f"(x));
    return y;
}

__global__ __launch_bounds__(256) void attn_kernel(
    const float* __restrict__ qr, const float* __restrict__ qi,
    const float* __restrict__ kr, const float* __restrict__ ki,
    const float* __restrict__ vr, const float* __restrict__ vi,
    float* __restrict__ out_r, float* __restrict__ out_i)
{
    extern __shared__ float sh[];
    float* sQr = sh;                 // [d][i], 64*SP
    float* sQi = sQr + 64 * SP;
    float* sKr = sQi + 64 * SP;      // K as [d][j]; reused as V [k][d]
    float* sKi = sKr + 64 * SP;
    float* sPp = sKi + 64 * SP;      // P transposed [j][i]
    float* sM  = sPp + 64 * SP;      // running max (base-2 domain)
    float* sL  = sM + 64;            // running denom
    float* sC  = sL + 64;            // per-tile rescale factor

    const int tid = threadIdx.x;
    const int tx = tid & 15;         // d / key micro-tile
    const int ty = tid >> 4;         // query micro-tile
    const int q0 = blockIdx.x * 64;
    const int bh = blockIdx.y;
    const int b  = bh / Hsz;
    const int h  = bh % Hsz;
    const size_t base = (size_t)b * Lsz * Esz + (size_t)h * Dsz;

    if (tid < 64) { sM[tid] = -INFINITY; sL[tid] = 0.f; }

    // load Q tile transposed: sQ[d][i]
    #pragma unroll
    for (int it = 0; it < 16; ++it) {
        int idx = tid + it * 256;
        int i = idx >> 6, d = idx & 63;
        size_t g = base + (size_t)(q0 + i) * Esz + d;
        sQr[d * SP + i] = qr[g];
        sQi[d * SP + i] = qi[g];
    }

    float oR[4][4] = {};
    float oI[4][4] = {};
    const float sc = 0.125f * 1.4426950408889634f;   // (1/sqrt(64)) * log2(e)

    for (int kt = 0; kt < Lsz; kt += 64) {
        __syncthreads();   // prior O-accum done reading sK (V) / first-iter Q stores visible
        // load K tile transposed: sK[d][j]
        #pragma unroll
        for (int it = 0; it < 16; ++it) {
            int idx = tid + it * 256;
            int j = idx >> 6, d = idx & 63;
            size_t g = base + (size_t)(kt + j) * Esz + d;
            sKr[d * SP + j] = kr[g];
            sKi[d * SP + j] = ki[g];
        }
        __syncthreads();

        // scores fragment
        float s[4][4] = {};
        #pragma unroll 4
        for (int d = 0; d < 64; ++d) {
            float4 a4 = *(const float4*)&sQr[d * SP + (ty << 2)];
            float4 c4 = *(const float4*)&sQi[d * SP + (ty << 2)];
            float4 u4 = *(const float4*)&sKr[d * SP + (tx << 2)];
            float4 v4 = *(const float4*)&sKi[d * SP + (tx << 2)];
            float aq[4] = {a4.x, a4.y, a4.z, a4.w};
            float bq[4] = {c4.x, c4.y, c4.z, c4.w};
            float ak[4] = {u4.x, u4.y, u4.z, u4.w};
            float bk[4] = {v4.x, v4.y, v4.z, v4.w};
            #pragma unroll
            for (int i = 0; i < 4; ++i) {
                #pragma unroll
                for (int j = 0; j < 4; ++j) {
                    s[i][j] = fmaf(aq[i], ak[j], s[i][j]);
                    s[i][j] = fmaf(bq[i], bk[j], s[i][j]);
                }
            }
        }
        // write scaled scores transposed: sP[j][i]
        #pragma unroll
        for (int j = 0; j < 4; ++j)
            #pragma unroll
            for (int i = 0; i < 4; ++i)
                sPp[((tx << 2) + j) * SP + (ty << 2) + i] = s[i][j] * sc;
        __syncthreads();

        // online softmax: 4 threads per query row (same warp -> shfl reduce)
        {
            int row  = tid >> 2;
            int part = tid & 3;
            float pm = -INFINITY;
            #pragma unroll
            for (int j = 0; j < 16; ++j)
                pm = fmaxf(pm, sPp[(part * 16 + j) * SP + row]);
            pm = fmaxf(pm, __shfl_xor_sync(0xffffffffu, pm, 1));
            pm = fmaxf(pm, __shfl_xor_sync(0xffffffffu, pm, 2));
            float mold = sM[row];
            float mnew = fmaxf(mold, pm);
            float psum = 0.f;
            #pragma unroll
            for (int j = 0; j < 16; ++j) {
                int jj = part * 16 + j;
                float p = fexp2(sPp[jj * SP + row] - mnew);
                sPp[jj * SP + row] = p;
                psum += p;
            }
            psum += __shfl_xor_sync(0xffffffffu, psum, 1);
            psum += __shfl_xor_sync(0xffffffffu, psum, 2);
            if (part == 0) {
                float c = fexp2(mold - mnew);
                sC[row] = c;
                sM[row] = mnew;
                sL[row] = sL[row] * c + psum;
            }
        }
        __syncthreads();

        // rescale O accumulators
        float cc[4];
        #pragma unroll
        for (int i = 0; i < 4; ++i) cc[i] = sC[(ty << 2) + i];
        #pragma unroll
        for (int i = 0; i < 4; ++i)
            #pragma unroll
            for (int j = 0; j < 4; ++j) { oR[i][j] *= cc[i]; oI[i][j] *= cc[i]; }

        // load V tile natural layout [k][d] into the K buffers
        #pragma unroll
        for (int it = 0; it < 16; ++it) {
            int idx = tid + it * 256;
            int k = idx >> 6, d = idx & 63;
            size_t g = base + (size_t)(kt + k) * Esz + d;
            sKr[k * SP + d] = vr[g];
            sKi[k * SP + d] = vi[g];
        }
        __syncthreads();

        // O += P @ V
        #pragma unroll 4
        for (int k = 0; k < 64; ++k) {
            float4 p4 = *(const float4*)&sPp[k * SP + (ty << 2)];
            float4 u4 = *(const float4*)&sKr[k * SP + (tx << 2)];
            float4 v4 = *(const float4*)&sKi[k * SP + (tx << 2)];
            float pv[4] = {p4.x, p4.y, p4.z, p4.w};
            float uv[4] = {u4.x, u4.y, u4.z, u4.w};
            float vv[4] = {v4.x, v4.y, v4.z, v4.w};
            #pragma unroll
            for (int i = 0; i < 4; ++i) {
                #pragma unroll
                for (int j = 0; j < 4; ++j) {
                    oR[i][j] = fmaf(pv[i], uv[j], oR[i][j]);
                    oI[i][j] = fmaf(pv[i], vv[j], oI[i][j]);
                }
            }
        }
    }

    // finalize: divide by l and store (sL stable since post-softmax sync of last tile)
    float invl[4];
    #pragma unroll
    for (int i = 0; i < 4; ++i) invl[i] = 1.0f / sL[(ty << 2) + i];
    #pragma unroll
    for (int i = 0; i < 4; ++i) {
        size_t g = base + (size_t)(q0 + (ty << 2) + i) * Esz + (tx << 2);
        *(float4*)&out_r[g] = make_float4(oR[i][0] * invl[i], oR[i][1] * invl[i],
                                          oR[i][2] * invl[i], oR[i][3] * invl[i]);
        *(float4*)&out_i[g] = make_float4(oI[i][0] * invl[i], oI[i][1] * invl[i],
                                          oI[i][2] * invl[i], oI[i][3] * invl[i]);
    }
}

// ---------------------------------------------------------------------------
extern "C" void kernel_launch(void* const* d_in, const int* in_sizes, int n_in,
                              void* d_out, int out_size)
{
    (void)in_sizes; (void)n_in; (void)out_size;
    const float* query_r = (const float*)d_in[0];
    const float* query_i = (const float*)d_in[1];
    const float* key_r   = (const float*)d_in[2];
    const float* key_i   = (const float*)d_in[3];
    const float* value_r = (const float*)d_in[4];
    const float* value_i = (const float*)d_in[5];
    const float* Wq_r = (const float*)d_in[6];
    const float* Wq_i = (const float*)d_in[7];
    const float* bq_r = (const float*)d_in[8];
    const float* bq_i = (const float*)d_in[9];
    const float* Wk_r = (const float*)d_in[10];
    const float* Wk_i = (const float*)d_in[11];
    const float* bk_r = (const float*)d_in[12];
    const float* bk_i = (const float*)d_in[13];
    const float* Wv_r = (const float*)d_in[14];
    const float* Wv_i = (const float*)d_in[15];
    const float* bv_r = (const float*)d_in[16];
    const float* bv_i = (const float*)d_in[17];
    const float* Wo_r = (const float*)d_in[18];
    const float* Wo_i = (const float*)d_in[19];
    const float* bo_r = (const float*)d_in[20];
    const float* bo_i = (const float*)d_in[21];

    float* scratch = nullptr;
    cudaGetSymbolAddress((void**)&scratch, g_scratch);
    float* gqr = scratch + 0ull * BLE;
    float* gqi = scratch + 1ull * BLE;
    float* gkr = scratch + 2ull * BLE;
    float* gki = scratch + 3ull * BLE;
    float* gvr = scratch + 4ull * BLE;
    float* gvi = scratch + 5ull * BLE;
    float* gor = scratch + 6ull * BLE;
    float* goi = scratch + 7ull * BLE;

    dim3 gg(Esz / BN, NROW / BM);   // (16, 64)
    cgemm_kernel<<<gg, 256>>>(query_r, query_i, Wq_r, Wq_i, bq_r, bq_i, gqr, gqi);
    cgemm_kernel<<<gg, 256>>>(key_r,   key_i,   Wk_r, Wk_i, bk_r, bk_i, gkr, gki);
    cgemm_kernel<<<gg, 256>>>(value_r, value_i, Wv_r, Wv_i, bv_r, bv_i, gvr, gvi);

    const int shbytes = (5 * 64 * SP + 192) * (int)sizeof(float);  // 87808
    cudaFuncSetAttribute((const void*)attn_kernel,
                         cudaFuncAttributeMaxDynamicSharedMemorySize, shbytes);
    attn_kernel<<<dim3(Lsz / 64, Bsz * Hsz), 256, shbytes>>>(
        gqr, gqi, gkr, gki, gvr, gvi, gor, goi);

    float* yr = (float*)d_out;
    float* yi = yr + BLE;
    cgemm_kernel<<<gg, 256>>>(gor, goi, Wo_r, Wo_i, bo_r, bo_i, yr, yi);
}

// round 3
// speedup vs baseline: 1.3059x; 1.3059x over previous
#include <cuda_runtime.h>
#include <cuda_bf16.h>
#include <math.h>
#include <cstdint>

#define Bsz 2
#define Lsz 2048
#define Esz 1024
#define Hsz 16
#define Dsz 64
#define NROW 4096               // Bsz*Lsz
#define BLE  (Bsz*Lsz*Esz)      // 4,194,304
#define KE   6144               // concatenated split-K (6 blocks of 1024)

// fp32 scratch: qr qi kr ki vr vi or oi
__device__ float g_scratch[8u * BLE];
// concatenated-K A matrix (reused for q, k, v, attn-out)
__device__ __nv_bfloat16 g_acat[(size_t)NROW * KE];           // 50 MB
// weight B matrices: 4 layers x {B1, B2}, each [Esz, KE]
__device__ __nv_bfloat16 g_bcat[8ull * Esz * KE];             // 100 MB

// ---------------------------------------------------------------------------
// helpers
// ---------------------------------------------------------------------------
__device__ __forceinline__ uint32_t smem_u32(const void* p) {
    uint32_t a;
    asm("{ .reg .u64 t; cvta.to.shared.u64 t, %1; cvt.u32.u64 %0, t; }" : "=r"(a) : "l"(p));
    return a;
}
__device__ __forceinline__ void cpa16(uint32_t dst, const void* src) {
    asm volatile("cp.async.cg.shared.global [%0], [%1], 16;" :: "r"(dst), "l"(src));
}
#define CPA_COMMIT() asm volatile("cp.async.commit_group;" ::: "memory")
#define CPA_WAIT(n)  asm volatile("cp.async.wait_group %0;" :: "n"(n) : "memory")

__device__ __forceinline__ void ldsm_x4(uint32_t* r, uint32_t addr) {
    asm volatile("ldmatrix.sync.aligned.m8n8.x4.shared.b16 {%0,%1,%2,%3}, [%4];"
        : "=r"(r[0]), "=r"(r[1]), "=r"(r[2]), "=r"(r[3]) : "r"(addr));
}
__device__ __forceinline__ void mma16816(float* c, const uint32_t* a, const uint32_t* b) {
    asm volatile("mma.sync.aligned.m16n8k16.row.col.f32.bf16.bf16.f32 "
        "{%0,%1,%2,%3}, {%4,%5,%6,%7}, {%8,%9}, {%0,%1,%2,%3};"
        : "+f"(c[0]), "+f"(c[1]), "+f"(c[2]), "+f"(c[3])
        : "r"(a[0]), "r"(a[1]), "r"(a[2]), "r"(a[3]), "r"(b[0]), "r"(b[1]));
}

__device__ __forceinline__ void split1(float x, __nv_bfloat16& h, __nv_bfloat16& l) {
    h = __float2bfloat16(x);
    l = __float2bfloat16(x - __bfloat162float(h));
}
__device__ __forceinline__ void store4(__nv_bfloat16* p, __nv_bfloat16 a, __nv_bfloat16 b,
                                       __nv_bfloat16 c, __nv_bfloat16 d) {
    __nv_bfloat162 u, v;
    u.x = a; u.y = b; v.x = c; v.y = d;
    uint2 w;
    w.x = *(uint32_t*)&u; w.y = *(uint32_t*)&v;
    *(uint2*)p = w;
}

// ---------------------------------------------------------------------------
// split kernels: build concatenated-K operands
// A_cat blocks: [Xr_h | Xr_h | Xr_l | Xi_h | Xi_h | Xi_l]
// ---------------------------------------------------------------------------
__global__ __launch_bounds__(256) void splitA_kernel(
    const float* __restrict__ Xr, const float* __restrict__ Xi,
    __nv_bfloat16* __restrict__ A)
{
    const int total = NROW * Esz / 4;
    int idx = blockIdx.x * 256 + threadIdx.x;
    const int stride = gridDim.x * 256;
    for (; idx < total; idx += stride) {
        const int m = idx >> 8;                 // Esz/4 = 256 float4 per row
        const int kq = (idx & 255) << 2;
        float4 xr = ((const float4*)Xr)[idx];
        float4 xi = ((const float4*)Xi)[idx];
        __nv_bfloat16 rh[4], rl[4], ih[4], il[4];
        split1(xr.x, rh[0], rl[0]); split1(xr.y, rh[1], rl[1]);
        split1(xr.z, rh[2], rl[2]); split1(xr.w, rh[3], rl[3]);
        split1(xi.x, ih[0], il[0]); split1(xi.y, ih[1], il[1]);
        split1(xi.z, ih[2], il[2]); split1(xi.w, ih[3], il[3]);
        __nv_bfloat16* base = A + (size_t)m * KE + kq;
        store4(base + 0,    rh[0], rh[1], rh[2], rh[3]);
        store4(base + 1024, rh[0], rh[1], rh[2], rh[3]);
        store4(base + 2048, rl[0], rl[1], rl[2], rl[3]);
        store4(base + 3072, ih[0], ih[1], ih[2], ih[3]);
        store4(base + 4096, ih[0], ih[1], ih[2], ih[3]);
        store4(base + 5120, il[0], il[1], il[2], il[3]);
    }
}

// B1 blocks: [Wr_h | Wr_l | Wr_h | -Wi_h | -Wi_l | -Wi_h]   (for Yr)
// B2 blocks: [Wi_h | Wi_l | Wi_h |  Wr_h |  Wr_l |  Wr_h]   (for Yi)
__global__ __launch_bounds__(256) void splitW_kernel(
    const float* __restrict__ Wr, const float* __restrict__ Wi,
    __nv_bfloat16* __restrict__ B1, __nv_bfloat16* __restrict__ B2)
{
    const int total = Esz * Esz / 4;
    int idx = blockIdx.x * 256 + threadIdx.x;
    const int stride = gridDim.x * 256;
    for (; idx < total; idx += stride) {
        const int n = idx >> 8;
        const int kq = (idx & 255) << 2;
        float4 wr = ((const float4*)Wr)[idx];
        float4 wi = ((const float4*)Wi)[idx];
        __nv_bfloat16 rh[4], rl[4], ih[4], il[4], nh[4], nl[4];
        split1(wr.x, rh[0], rl[0]); split1(wr.y, rh[1], rl[1]);
        split1(wr.z, rh[2], rl[2]); split1(wr.w, rh[3], rl[3]);
        split1(wi.x, ih[0], il[0]); split1(wi.y, ih[1], il[1]);
        split1(wi.z, ih[2], il[2]); split1(wi.w, ih[3], il[3]);
        split1(-wi.x, nh[0], nl[0]); split1(-wi.y, nh[1], nl[1]);
        split1(-wi.z, nh[2], nl[2]); split1(-wi.w, nh[3], nl[3]);
        __nv_bfloat16* b1 = B1 + (size_t)n * KE + kq;
        __nv_bfloat16* b2 = B2 + (size_t)n * KE + kq;
        store4(b1 + 0,    rh[0], rh[1], rh[2], rh[3]);
        store4(b1 + 1024, rl[0], rl[1], rl[2], rl[3]);
        store4(b1 + 2048, rh[0], rh[1], rh[2], rh[3]);
        store4(b1 + 3072, nh[0], nh[1], nh[2], nh[3]);
        store4(b1 + 4096, nl[0], nl[1], nl[2], nl[3]);
        store4(b1 + 5120, nh[0], nh[1], nh[2], nh[3]);
        store4(b2 + 0,    ih[0], ih[1], ih[2], ih[3]);
        store4(b2 + 1024, il[0], il[1], il[2], il[3]);
        store4(b2 + 2048, ih[0], ih[1], ih[2], ih[3]);
        store4(b2 + 3072, rh[0], rh[1], rh[2], rh[3]);
        store4(b2 + 4096, rl[0], rl[1], rl[2], rl[3]);
        store4(b2 + 5120, rh[0], rh[1], rh[2], rh[3]);
    }
}

// ---------------------------------------------------------------------------
// GEMM: Yr = A @ B1^T + br,  Yi = A @ B2^T + bi   (A:[4096,KE], B:[1024,KE])
// CTA tile 128x64, K-chunk 64, cp.async double buffer, mma.sync bf16.
// ---------------------------------------------------------------------------
#define GM 128
#define GN 64
#define KCH 64
#define NCHK (KE / KCH)                 // 96
#define ASTR 144                        // bytes per smem row (64 bf16 + 8 pad)
#define A_BYTES (GM * ASTR)             // 18432
#define B_BYTES (GN * ASTR)             // 9216
#define STAGE (A_BYTES + 2 * B_BYTES)   // 36864
#define GEMM_SMEM (2 * STAGE)           // 73728

__global__ __launch_bounds__(256, 1) void gemm_kernel(
    const __nv_bfloat16* __restrict__ A,
    const __nv_bfloat16* __restrict__ B1,
    const __nv_bfloat16* __restrict__ B2,
    const float* __restrict__ br, const float* __restrict__ bi,
    float* __restrict__ Yr, float* __restrict__ Yi)
{
    extern __shared__ char smem[];
    const uint32_t sb = smem_u32(smem);
    const int tid = threadIdx.x;
    const int lane = tid & 31;
    const int wid = tid >> 5;
    const int wm = wid >> 1;            // 0..3
    const int wn = wid & 1;             // 0..1
    const int m0 = blockIdx.y * GM;
    const int n0 = blockIdx.x * GN;

    // loader mapping: per 256-thread pass, op -> (row, 16B-chunk)
    auto load_chunk = [&](int c, int buf) {
        const uint32_t s = sb + buf * STAGE;
        const int kc = c * KCH;
        #pragma unroll
        for (int i = 0; i < 4; ++i) {
            const int op = tid + i * 256;
            const int r = op >> 3, q = op & 7;
            cpa16(s + r * ASTR + q * 16, A + (size_t)(m0 + r) * KE + kc + q * 8);
        }
        #pragma unroll
        for (int i = 0; i < 2; ++i) {
            const int op = tid + i * 256;
            const int r = op >> 3, q = op & 7;
            cpa16(s + A_BYTES + r * ASTR + q * 16,
                  B1 + (size_t)(n0 + r) * KE + kc + q * 8);
            cpa16(s + A_BYTES + B_BYTES + r * ASTR + q * 16,
                  B2 + (size_t)(n0 + r) * KE + kc + q * 8);
        }
        CPA_COMMIT();
    };

    float acc[2][2][4][4] = {};   // [out][mtile][ntile][frag]

    // ldmatrix lane address components
    const uint32_t aRowOff = (uint32_t)(wm * 32 + (lane & 15));
    const uint32_t aColB   = (uint32_t)((lane >> 4) * 8 * 2);
    const uint32_t bRowOff = (uint32_t)(wn * 32 + (lane & 7) + ((lane >> 4) << 3));
    const uint32_t bColB   = (uint32_t)(((lane >> 3) & 1) * 8 * 2);

    load_chunk(0, 0);

    for (int c = 0; c < NCHK; ++c) {
        if (c + 1 < NCHK) {
            load_chunk(c + 1, (c + 1) & 1);
            CPA_WAIT(1);
        } else {
            CPA_WAIT(0);
        }
        __syncthreads();

        const uint32_t s = sb + (c & 1) * STAGE;
        const uint32_t aB = s + aRowOff * ASTR + aColB;
        const uint32_t bB = s + A_BYTES + bRowOff * ASTR + bColB;

        #pragma unroll
        for (int ks = 0; ks < 4; ++ks) {
            uint32_t a0[4], a1[4];
            ldsm_x4(a0, aB + ks * 32);
            ldsm_x4(a1, aB + 16 * ASTR + ks * 32);
            uint32_t bf[2][2][4];
            #pragma unroll
            for (int o = 0; o < 2; ++o)
                #pragma unroll
                for (int np = 0; np < 2; ++np)
                    ldsm_x4(bf[o][np], bB + o * B_BYTES + np * 16 * ASTR + ks * 32);
            #pragma unroll
            for (int o = 0; o < 2; ++o)
                #pragma unroll
                for (int nt = 0; nt < 4; ++nt) {
                    mma16816(acc[o][0][nt], a0, &bf[o][nt >> 1][(nt & 1) * 2]);
                    mma16816(acc[o][1][nt], a1, &bf[o][nt >> 1][(nt & 1) * 2]);
                }
        }
        __syncthreads();
    }

    // epilogue: c-frag (row=l/4, col=2*(l%4)) (+8 rows for c2,c3)
    const int rowb = m0 + wm * 32 + (lane >> 2);
    const int colb = n0 + wn * 32 + (lane & 3) * 2;
    #pragma unroll
    for (int mt = 0; mt < 2; ++mt) {
        #pragma unroll
        for (int nt = 0; nt < 4; ++nt) {
            const int col = colb + nt * 8;
            const int row = rowb + mt * 16;
            const float br0 = br[col], br1 = br[col + 1];
            const float bi0 = bi[col], bi1 = bi[col + 1];
            float2 v;
            v.x = acc[0][mt][nt][0] + br0; v.y = acc[0][mt][nt][1] + br1;
            *(float2*)&Yr[(size_t)row * Esz + col] = v;
            v.x = acc[0][mt][nt][2] + br0; v.y = acc[0][mt][nt][3] + br1;
            *(float2*)&Yr[(size_t)(row + 8) * Esz + col] = v;
            v.x = acc[1][mt][nt][0] + bi0; v.y = acc[1][mt][nt][1] + bi1;
            *(float2*)&Yi[(size_t)row * Esz + col] = v;
            v.x = acc[1][mt][nt][2] + bi0; v.y = acc[1][mt][nt][3] + bi1;
            *(float2*)&Yi[(size_t)(row + 8) * Esz + col] = v;
        }
    }
}

// ---------------------------------------------------------------------------
// Flash attention (fp32 — unchanged, passing at rel_err 3e-6)
// ---------------------------------------------------------------------------
#define SP 68

__device__ __forceinline__ float fexp2(float x) {
    float y;
    asm("ex2.approx.ftz.f32 %0, %1;" : "=f"(y) : "f"(x));
    return y;
}

__global__ __launch_bounds__(256) void attn_kernel(
    const float* __restrict__ qr, const float* __restrict__ qi,
    const float* __restrict__ kr, const float* __restrict__ ki,
    const float* __restrict__ vr, const float* __restrict__ vi,
    float* __restrict__ out_r, float* __restrict__ out_i)
{
    extern __shared__ float sh[];
    float* sQr = sh;
    float* sQi = sQr + 64 * SP;
    float* sKr = sQi + 64 * SP;
    float* sKi = sKr + 64 * SP;
    float* sPp = sKi + 64 * SP;
    float* sM  = sPp + 64 * SP;
    float* sL  = sM + 64;
    float* sC  = sL + 64;

    const int tid = threadIdx.x;
    const int tx = tid & 15;
    const int ty = tid >> 4;
    const int q0 = blockIdx.x * 64;
    const int bh = blockIdx.y;
    const int b  = bh / Hsz;
    const int h  = bh % Hsz;
    const size_t base = (size_t)b * Lsz * Esz + (size_t)h * Dsz;

    if (tid < 64) { sM[tid] = -INFINITY; sL[tid] = 0.f; }

    #pragma unroll
    for (int it = 0; it < 16; ++it) {
        int idx = tid + it * 256;
        int i = idx >> 6, d = idx & 63;
        size_t g = base + (size_t)(q0 + i) * Esz + d;
        sQr[d * SP + i] = qr[g];
        sQi[d * SP + i] = qi[g];
    }

    float oR[4][4] = {};
    float oI[4][4] = {};
    const float sc = 0.125f * 1.4426950408889634f;

    for (int kt = 0; kt < Lsz; kt += 64) {
        __syncthreads();
        #pragma unroll
        for (int it = 0; it < 16; ++it) {
            int idx = tid + it * 256;
            int j = idx >> 6, d = idx & 63;
            size_t g = base + (size_t)(kt + j) * Esz + d;
            sKr[d * SP + j] = kr[g];
            sKi[d * SP + j] = ki[g];
        }
        __syncthreads();

        float s[4][4] = {};
        #pragma unroll 4
        for (int d = 0; d < 64; ++d) {
            float4 a4 = *(const float4*)&sQr[d * SP + (ty << 2)];
            float4 c4 = *(const float4*)&sQi[d * SP + (ty << 2)];
            float4 u4 = *(const float4*)&sKr[d * SP + (tx << 2)];
            float4 v4 = *(const float4*)&sKi[d * SP + (tx << 2)];
            float aq[4] = {a4.x, a4.y, a4.z, a4.w};
            float bq[4] = {c4.x, c4.y, c4.z, c4.w};
            float ak[4] = {u4.x, u4.y, u4.z, u4.w};
            float bk[4] = {v4.x, v4.y, v4.z, v4.w};
            #pragma unroll
            for (int i = 0; i < 4; ++i)
                #pragma unroll
                for (int j = 0; j < 4; ++j) {
                    s[i][j] = fmaf(aq[i], ak[j], s[i][j]);
                    s[i][j] = fmaf(bq[i], bk[j], s[i][j]);
                }
        }
        #pragma unroll
        for (int j = 0; j < 4; ++j)
            #pragma unroll
            for (int i = 0; i < 4; ++i)
                sPp[((tx << 2) + j) * SP + (ty << 2) + i] = s[i][j] * sc;
        __syncthreads();

        {
            int row  = tid >> 2;
            int part = tid & 3;
            float pm = -INFINITY;
            #pragma unroll
            for (int j = 0; j < 16; ++j)
                pm = fmaxf(pm, sPp[(part * 16 + j) * SP + row]);
            pm = fmaxf(pm, __shfl_xor_sync(0xffffffffu, pm, 1));
            pm = fmaxf(pm, __shfl_xor_sync(0xffffffffu, pm, 2));
            float mold = sM[row];
            float mnew = fmaxf(mold, pm);
            float psum = 0.f;
            #pragma unroll
            for (int j = 0; j < 16; ++j) {
                int jj = part * 16 + j;
                float p = fexp2(sPp[jj * SP + row] - mnew);
                sPp[jj * SP + row] = p;
                psum += p;
            }
            psum += __shfl_xor_sync(0xffffffffu, psum, 1);
            psum += __shfl_xor_sync(0xffffffffu, psum, 2);
            if (part == 0) {
                float c = fexp2(mold - mnew);
                sC[row] = c;
                sM[row] = mnew;
                sL[row] = sL[row] * c + psum;
            }
        }
        __syncthreads();

        float cc[4];
        #pragma unroll
        for (int i = 0; i < 4; ++i) cc[i] = sC[(ty << 2) + i];
        #pragma unroll
        for (int i = 0; i < 4; ++i)
            #pragma unroll
            for (int j = 0; j < 4; ++j) { oR[i][j] *= cc[i]; oI[i][j] *= cc[i]; }

        #pragma unroll
        for (int it = 0; it < 16; ++it) {
            int idx = tid + it * 256;
            int k = idx >> 6, d = idx & 63;
            size_t g = base + (size_t)(kt + k) * Esz + d;
            sKr[k * SP + d] = vr[g];
            sKi[k * SP + d] = vi[g];
        }
        __syncthreads();

        #pragma unroll 4
        for (int k = 0; k < 64; ++k) {
            float4 p4 = *(const float4*)&sPp[k * SP + (ty << 2)];
            float4 u4 = *(const float4*)&sKr[k * SP + (tx << 2)];
            float4 v4 = *(const float4*)&sKi[k * SP + (tx << 2)];
            float pv[4] = {p4.x, p4.y, p4.z, p4.w};
            float uv[4] = {u4.x, u4.y, u4.z, u4.w};
            float vv[4] = {v4.x, v4.y, v4.z, v4.w};
            #pragma unroll
            for (int i = 0; i < 4; ++i)
                #pragma unroll
                for (int j = 0; j < 4; ++j) {
                    oR[i][j] = fmaf(pv[i], uv[j], oR[i][j]);
                    oI[i][j] = fmaf(pv[i], vv[j], oI[i][j]);
                }
        }
    }

    float invl[4];
    #pragma unroll
    for (int i = 0; i < 4; ++i) invl[i] = 1.0f / sL[(ty << 2) + i];
    #pragma unroll
    for (int i = 0; i < 4; ++i) {
        size_t g = base + (size_t)(q0 + (ty << 2) + i) * Esz + (tx << 2);
        *(float4*)&out_r[g] = make_float4(oR[i][0] * invl[i], oR[i][1] * invl[i],
                                          oR[i][2] * invl[i], oR[i][3] * invl[i]);
        *(float4*)&out_i[g] = make_float4(oI[i][0] * invl[i], oI[i][1] * invl[i],
                                          oI[i][2] * invl[i], oI[i][3] * invl[i]);
    }
}

// ---------------------------------------------------------------------------
extern "C" void kernel_launch(void* const* d_in, const int* in_sizes, int n_in,
                              void* d_out, int out_size)
{
    (void)in_sizes; (void)n_in; (void)out_size;
    const float* query_r = (const float*)d_in[0];
    const float* query_i = (const float*)d_in[1];
    const float* key_r   = (const float*)d_in[2];
    const float* key_i   = (const float*)d_in[3];
    const float* value_r = (const float*)d_in[4];
    const float* value_i = (const float*)d_in[5];
    const float* Wq_r = (const float*)d_in[6];
    const float* Wq_i = (const float*)d_in[7];
    const float* bq_r = (const float*)d_in[8];
    const float* bq_i = (const float*)d_in[9];
    const float* Wk_r = (const float*)d_in[10];
    const float* Wk_i = (const float*)d_in[11];
    const float* bk_r = (const float*)d_in[12];
    const float* bk_i = (const float*)d_in[13];
    const float* Wv_r = (const float*)d_in[14];
    const float* Wv_i = (const float*)d_in[15];
    const float* bv_r = (const float*)d_in[16];
    const float* bv_i = (const float*)d_in[17];
    const float* Wo_r = (const float*)d_in[18];
    const float* Wo_i = (const float*)d_in[19];
    const float* bo_r = (const float*)d_in[20];
    const float* bo_i = (const float*)d_in[21];

    float* scratch = nullptr;
    cudaGetSymbolAddress((void**)&scratch, g_scratch);
    __nv_bfloat16* acat = nullptr;
    cudaGetSymbolAddress((void**)&acat, g_acat);
    __nv_bfloat16* bcat = nullptr;
    cudaGetSymbolAddress((void**)&bcat, g_bcat);

    float* gqr = scratch + 0ull * BLE;
    float* gqi = scratch + 1ull * BLE;
    float* gkr = scratch + 2ull * BLE;
    float* gki = scratch + 3ull * BLE;
    float* gvr = scratch + 4ull * BLE;
    float* gvi = scratch + 5ull * BLE;
    float* gor = scratch + 6ull * BLE;
    float* goi = scratch + 7ull * BLE;

    auto Wc = [&](int s) { return bcat + (size_t)s * Esz * KE; };

    // weight splits: slots {0,1}=q {2,3}=k {4,5}=v {6,7}=o
    splitW_kernel<<<512, 256>>>(Wq_r, Wq_i, Wc(0), Wc(1));
    splitW_kernel<<<512, 256>>>(Wk_r, Wk_i, Wc(2), Wc(3));
    splitW_kernel<<<512, 256>>>(Wv_r, Wv_i, Wc(4), Wc(5));
    splitW_kernel<<<512, 256>>>(Wo_r, Wo_i, Wc(6), Wc(7));

    cudaFuncSetAttribute((const void*)gemm_kernel,
                         cudaFuncAttributeMaxDynamicSharedMemorySize, GEMM_SMEM);
    dim3 gg(Esz / GN, NROW / GM);   // (16, 32)

    splitA_kernel<<<1024, 256>>>(query_r, query_i, acat);
    gemm_kernel<<<gg, 256, GEMM_SMEM>>>(acat, Wc(0), Wc(1), bq_r, bq_i, gqr, gqi);
    splitA_kernel<<<1024, 256>>>(key_r, key_i, acat);
    gemm_kernel<<<gg, 256, GEMM_SMEM>>>(acat, Wc(2), Wc(3), bk_r, bk_i, gkr, gki);
    splitA_kernel<<<1024, 256>>>(value_r, value_i, acat);
    gemm_kernel<<<gg, 256, GEMM_SMEM>>>(acat, Wc(4), Wc(5), bv_r, bv_i, gvr, gvi);

    const int shbytes = (5 * 64 * SP + 192) * (int)sizeof(float);
    cudaFuncSetAttribute((const void*)attn_kernel,
                         cudaFuncAttributeMaxDynamicSharedMemorySize, shbytes);
    attn_kernel<<<dim3(Lsz / 64, Bsz * Hsz), 256, shbytes>>>(
        gqr, gqi, gkr, gki, gvr, gvi, gor, goi);

    splitA_kernel<<<1024, 256>>>(gor, goi, acat);
    float* yr = (float*)d_out;
    float* yi = yr + BLE;
    gemm_kernel<<<gg, 256, GEMM_SMEM>>>(acat, Wc(6), Wc(7), bo_r, bo_i, yr, yi);
}

// round 4
// speedup vs baseline: 2.2525x; 1.7249x over previous
#include <cuda_runtime.h>
#include <cuda_bf16.h>
#include <math.h>
#include <cstdint>

#define Bsz 2
#define Lsz 2048
#define Esz 1024
#define Hsz 16
#define Dsz 64
#define NROW 4096               // Bsz*Lsz
#define BLE  (Bsz*Lsz*Esz)      // 4,194,304
#define KE   6144               // concatenated split-K
#define BHD  ((size_t)Bsz*Hsz*Lsz*Dsz)   // 4,194,304 per attn array

// fp32 scratch: qr qi kr ki vr vi or oi
__device__ float g_scratch[8u * BLE];
// concatenated-K A matrix (reused for q, k, v, attn-out)
__device__ __nv_bfloat16 g_acat[(size_t)NROW * KE];           // 50 MB
// weight B matrices: 4 layers x {B1, B2}, each [Esz, KE]
__device__ __nv_bfloat16 g_bcat[8ull * Esz * KE];             // 100 MB
// attention bf16 arrays: qrh qrl qih qil | krh krl kih kil | vrh vrl vih vil
__device__ __nv_bfloat16 g_attn[12ull * BHD];                 // 96 MB

// ---------------------------------------------------------------------------
// helpers
// ---------------------------------------------------------------------------
__device__ __forceinline__ uint32_t smem_u32(const void* p) {
    uint32_t a;
    asm("{ .reg .u64 t; cvta.to.shared.u64 t, %1; cvt.u32.u64 %0, t; }" : "=r"(a) : "l"(p));
    return a;
}
__device__ __forceinline__ void cpa16(uint32_t dst, const void* src) {
    asm volatile("cp.async.cg.shared.global [%0], [%1], 16;" :: "r"(dst), "l"(src));
}
#define CPA_COMMIT() asm volatile("cp.async.commit_group;" ::: "memory")
#define CPA_WAIT(n)  asm volatile("cp.async.wait_group %0;" :: "n"(n) : "memory")

__device__ __forceinline__ void ldsm_x4(uint32_t* r, uint32_t addr) {
    asm volatile("ldmatrix.sync.aligned.m8n8.x4.shared.b16 {%0,%1,%2,%3}, [%4];"
        : "=r"(r[0]), "=r"(r[1]), "=r"(r[2]), "=r"(r[3]) : "r"(addr));
}
__device__ __forceinline__ void ldsm_x4_t(uint32_t* r, uint32_t addr) {
    asm volatile("ldmatrix.sync.aligned.m8n8.x4.trans.shared.b16 {%0,%1,%2,%3}, [%4];"
        : "=r"(r[0]), "=r"(r[1]), "=r"(r[2]), "=r"(r[3]) : "r"(addr));
}
__device__ __forceinline__ void mma16816(float* c, const uint32_t* a, const uint32_t* b) {
    asm volatile("mma.sync.aligned.m16n8k16.row.col.f32.bf16.bf16.f32 "
        "{%0,%1,%2,%3}, {%4,%5,%6,%7}, {%8,%9}, {%0,%1,%2,%3};"
        : "+f"(c[0]), "+f"(c[1]), "+f"(c[2]), "+f"(c[3])
        : "r"(a[0]), "r"(a[1]), "r"(a[2]), "r"(a[3]), "r"(b[0]), "r"(b[1]));
}
__device__ __forceinline__ float fexp2(float x) {
    float y;
    asm("ex2.approx.ftz.f32 %0, %1;" : "=f"(y) : "f"(x));
    return y;
}
__device__ __forceinline__ void split1(float x, __nv_bfloat16& h, __nv_bfloat16& l) {
    h = __float2bfloat16(x);
    l = __float2bfloat16(x - __bfloat162float(h));
}
__device__ __forceinline__ uint32_t packbf(float a, float b) {
    __nv_bfloat162 t;
    t.x = __float2bfloat16(a); t.y = __float2bfloat16(b);
    return *(uint32_t*)&t;
}
__device__ __forceinline__ uint32_t packbf2(__nv_bfloat16 a, __nv_bfloat16 b) {
    __nv_bfloat162 t; t.x = a; t.y = b;
    return *(uint32_t*)&t;
}
__device__ __forceinline__ void store4(__nv_bfloat16* p, __nv_bfloat16 a, __nv_bfloat16 b,
                                       __nv_bfloat16 c, __nv_bfloat16 d) {
    uint2 w;
    w.x = packbf2(a, b); w.y = packbf2(c, d);
    *(uint2*)p = w;
}

// ---------------------------------------------------------------------------
// split kernels for GEMM operands (concatenated K)
// A_cat blocks: [Xr_h | Xr_h | Xr_l | Xi_h | Xi_h | Xi_l]
// ---------------------------------------------------------------------------
__global__ __launch_bounds__(256) void splitA_kernel(
    const float* __restrict__ Xr, const float* __restrict__ Xi,
    __nv_bfloat16* __restrict__ A)
{
    const int total = NROW * Esz / 4;
    int idx = blockIdx.x * 256 + threadIdx.x;
    const int stride = gridDim.x * 256;
    for (; idx < total; idx += stride) {
        const int m = idx >> 8;
        const int kq = (idx & 255) << 2;
        float4 xr = ((const float4*)Xr)[idx];
        float4 xi = ((const float4*)Xi)[idx];
        __nv_bfloat16 rh[4], rl[4], ih[4], il[4];
        split1(xr.x, rh[0], rl[0]); split1(xr.y, rh[1], rl[1]);
        split1(xr.z, rh[2], rl[2]); split1(xr.w, rh[3], rl[3]);
        split1(xi.x, ih[0], il[0]); split1(xi.y, ih[1], il[1]);
        split1(xi.z, ih[2], il[2]); split1(xi.w, ih[3], il[3]);
        __nv_bfloat16* base = A + (size_t)m * KE + kq;
        store4(base + 0,    rh[0], rh[1], rh[2], rh[3]);
        store4(base + 1024, rh[0], rh[1], rh[2], rh[3]);
        store4(base + 2048, rl[0], rl[1], rl[2], rl[3]);
        store4(base + 3072, ih[0], ih[1], ih[2], ih[3]);
        store4(base + 4096, ih[0], ih[1], ih[2], ih[3]);
        store4(base + 5120, il[0], il[1], il[2], il[3]);
    }
}

__global__ __launch_bounds__(256) void splitW_kernel(
    const float* __restrict__ Wr, const float* __restrict__ Wi,
    __nv_bfloat16* __restrict__ B1, __nv_bfloat16* __restrict__ B2)
{
    const int total = Esz * Esz / 4;
    int idx = blockIdx.x * 256 + threadIdx.x;
    const int stride = gridDim.x * 256;
    for (; idx < total; idx += stride) {
        const int n = idx >> 8;
        const int kq = (idx & 255) << 2;
        float4 wr = ((const float4*)Wr)[idx];
        float4 wi = ((const float4*)Wi)[idx];
        __nv_bfloat16 rh[4], rl[4], ih[4], il[4], nh[4], nl[4];
        split1(wr.x, rh[0], rl[0]); split1(wr.y, rh[1], rl[1]);
        split1(wr.z, rh[2], rl[2]); split1(wr.w, rh[3], rl[3]);
        split1(wi.x, ih[0], il[0]); split1(wi.y, ih[1], il[1]);
        split1(wi.z, ih[2], il[2]); split1(wi.w, ih[3], il[3]);
        split1(-wi.x, nh[0], nl[0]); split1(-wi.y, nh[1], nl[1]);
        split1(-wi.z, nh[2], nl[2]); split1(-wi.w, nh[3], nl[3]);
        __nv_bfloat16* b1 = B1 + (size_t)n * KE + kq;
        __nv_bfloat16* b2 = B2 + (size_t)n * KE + kq;
        store4(b1 + 0,    rh[0], rh[1], rh[2], rh[3]);
        store4(b1 + 1024, rl[0], rl[1], rl[2], rl[3]);
        store4(b1 + 2048, rh[0], rh[1], rh[2], rh[3]);
        store4(b1 + 3072, nh[0], nh[1], nh[2], nh[3]);
        store4(b1 + 4096, nl[0], nl[1], nl[2], nl[3]);
        store4(b1 + 5120, nh[0], nh[1], nh[2], nh[3]);
        store4(b2 + 0,    ih[0], ih[1], ih[2], ih[3]);
        store4(b2 + 1024, il[0], il[1], il[2], il[3]);
        store4(b2 + 2048, ih[0], ih[1], ih[2], ih[3]);
        store4(b2 + 3072, rh[0], rh[1], rh[2], rh[3]);
        store4(b2 + 4096, rl[0], rl[1], rl[2], rl[3]);
        store4(b2 + 5120, rh[0], rh[1], rh[2], rh[3]);
    }
}

// ---------------------------------------------------------------------------
// attention prep: fp32 [B,L,H*D] -> 4 bf16 arrays [BH][L][D] (hi/lo, r/i)
// ---------------------------------------------------------------------------
__global__ __launch_bounds__(256) void attprep_kernel(
    const float* __restrict__ xr, const float* __restrict__ xi,
    __nv_bfloat16* __restrict__ rh, __nv_bfloat16* __restrict__ rl,
    __nv_bfloat16* __restrict__ ih, __nv_bfloat16* __restrict__ il)
{
    const int total = NROW * Esz / 4;
    int idx = blockIdx.x * 256 + threadIdx.x;
    const int stride = gridDim.x * 256;
    for (; idx < total; idx += stride) {
        const int m = idx >> 8;            // b*L + l
        const int e = (idx & 255) << 2;
        const int b = m >> 11, l = m & 2047;
        const int h = e >> 6, d = e & 63;
        const size_t o = (((size_t)(b * Hsz + h) * Lsz) + l) * Dsz + d;
        float4 vr = ((const float4*)xr)[idx];
        float4 vi = ((const float4*)xi)[idx];
        __nv_bfloat16 a[4], c[4], p[4], q[4];
        split1(vr.x, a[0], c[0]); split1(vr.y, a[1], c[1]);
        split1(vr.z, a[2], c[2]); split1(vr.w, a[3], c[3]);
        split1(vi.x, p[0], q[0]); split1(vi.y, p[1], q[1]);
        split1(vi.z, p[2], q[2]); split1(vi.w, p[3], q[3]);
        store4(rh + o, a[0], a[1], a[2], a[3]);
        store4(rl + o, c[0], c[1], c[2], c[3]);
        store4(ih + o, p[0], p[1], p[2], p[3]);
        store4(il + o, q[0], q[1], q[2], q[3]);
    }
}

// ---------------------------------------------------------------------------
// GEMM: Yr = A @ B1^T + br,  Yi = A @ B2^T + bi   (A:[4096,KE], B:[1024,KE])
// CTA tile 128x128, K-chunk 64, cp.async double buffer, mma.sync bf16.
// ---------------------------------------------------------------------------
#define GM 128
#define GN 128
#define KCH 64
#define NCHK (KE / KCH)                 // 96
#define ASTR 144
#define A_BYTES (GM * ASTR)             // 18432
#define B_BYTES (GN * ASTR)             // 18432
#define STAGE (A_BYTES + 2 * B_BYTES)   // 55296
#define GEMM_SMEM (2 * STAGE)           // 110592

__global__ __launch_bounds__(256, 1) void gemm_kernel(
    const __nv_bfloat16* __restrict__ A,
    const __nv_bfloat16* __restrict__ B1,
    const __nv_bfloat16* __restrict__ B2,
    const float* __restrict__ br, const float* __restrict__ bi,
    float* __restrict__ Yr, float* __restrict__ Yi)
{
    extern __shared__ char smem[];
    const uint32_t sb = smem_u32(smem);
    const int tid = threadIdx.x;
    const int lane = tid & 31;
    const int wid = tid >> 5;
    const int wm = wid >> 2;            // 0..1
    const int wn = wid & 3;             // 0..3
    const int m0 = blockIdx.y * GM;
    const int n0 = blockIdx.x * GN;

    auto load_chunk = [&](int c, int buf) {
        const uint32_t s = sb + buf * STAGE;
        const int kc = c * KCH;
        #pragma unroll
        for (int i = 0; i < 4; ++i) {
            const int op = tid + i * 256;
            const int r = op >> 3, q = op & 7;
            cpa16(s + r * ASTR + q * 16, A + (size_t)(m0 + r) * KE + kc + q * 8);
        }
        #pragma unroll
        for (int i = 0; i < 4; ++i) {
            const int op = tid + i * 256;
            const int r = op >> 3, q = op & 7;
            cpa16(s + A_BYTES + r * ASTR + q * 16,
                  B1 + (size_t)(n0 + r) * KE + kc + q * 8);
            cpa16(s + A_BYTES + B_BYTES + r * ASTR + q * 16,
                  B2 + (size_t)(n0 + r) * KE + kc + q * 8);
        }
        CPA_COMMIT();
    };

    float acc[2][4][4][4] = {};   // [out][mtile][ntile][frag]

    const uint32_t aRowOff = (uint32_t)(wm * 64 + (lane & 15));
    const uint32_t aColB   = (uint32_t)((lane >> 4) * 16);
    const uint32_t bRowOff = (uint32_t)(wn * 32 + (lane & 7) + ((lane >> 4) << 3));
    const uint32_t bColB   = (uint32_t)(((lane >> 3) & 1) * 16);

    load_chunk(0, 0);

    for (int c = 0; c < NCHK; ++c) {
        if (c + 1 < NCHK) {
            load_chunk(c + 1, (c + 1) & 1);
            CPA_WAIT(1);
        } else {
            CPA_WAIT(0);
        }
        __syncthreads();

        const uint32_t s = sb + (c & 1) * STAGE;
        const uint32_t aB = s + aRowOff * ASTR + aColB;
        const uint32_t bB = s + A_BYTES + bRowOff * ASTR + bColB;

        #pragma unroll
        for (int ks = 0; ks < 4; ++ks) {
            uint32_t a[4][4];
            #pragma unroll
            for (int mt = 0; mt < 4; ++mt)
                ldsm_x4(a[mt], aB + mt * 16 * ASTR + ks * 32);
            uint32_t bf[2][2][4];
            #pragma unroll
            for (int o = 0; o < 2; ++o)
                #pragma unroll
                for (int np = 0; np < 2; ++np)
                    ldsm_x4(bf[o][np], bB + o * B_BYTES + np * 16 * ASTR + ks * 32);
            #pragma unroll
            for (int o = 0; o < 2; ++o)
                #pragma unroll
                for (int mt = 0; mt < 4; ++mt)
                    #pragma unroll
                    for (int nt = 0; nt < 4; ++nt)
                        mma16816(acc[o][mt][nt], a[mt], &bf[o][nt >> 1][(nt & 1) * 2]);
        }
        __syncthreads();
    }

    const int rowb = m0 + wm * 64 + (lane >> 2);
    const int colb = n0 + wn * 32 + (lane & 3) * 2;
    #pragma unroll
    for (int mt = 0; mt < 4; ++mt) {
        #pragma unroll
        for (int nt = 0; nt < 4; ++nt) {
            const int col = colb + nt * 8;
            const int row = rowb + mt * 16;
            const float br0 = __ldg(&br[col]), br1 = __ldg(&br[col + 1]);
            const float bi0 = __ldg(&bi[col]), bi1 = __ldg(&bi[col + 1]);
            float2 v;
            v.x = acc[0][mt][nt][0] + br0; v.y = acc[0][mt][nt][1] + br1;
            *(float2*)&Yr[(size_t)row * Esz + col] = v;
            v.x = acc[0][mt][nt][2] + br0; v.y = acc[0][mt][nt][3] + br1;
            *(float2*)&Yr[(size_t)(row + 8) * Esz + col] = v;
            v.x = acc[1][mt][nt][0] + bi0; v.y = acc[1][mt][nt][1] + bi1;
            *(float2*)&Yi[(size_t)row * Esz + col] = v;
            v.x = acc[1][mt][nt][2] + bi0; v.y = acc[1][mt][nt][3] + bi1;
            *(float2*)&Yi[(size_t)(row + 8) * Esz + col] = v;
        }
    }
}

// ---------------------------------------------------------------------------
// Tensor-core flash attention.
// Grid (L/128, B*H), 256 threads (8 warps x m16). K-tile 64.
// S = (Qr Kr^T + Qi Ki^T)*scale via 6 bf16 hi/lo mma chains, fp32 acc.
// Online softmax in fragments; P -> bf16 hi/lo A-frags; O += P V (6 chains).
// ---------------------------------------------------------------------------
#define AT_STR 144
#define AT_MAT (64 * AT_STR)                 // 9216
#define AT_QMAT (128 * AT_STR)               // 18432
#define AT_QBYTES (4 * AT_QMAT)              // 73728
#define AT_STAGE (8 * AT_MAT)                // 73728
#define AT_SMEM (AT_QBYTES + 2 * AT_STAGE)   // 221184
#define NKT (Lsz / 64)                       // 32

__global__ __launch_bounds__(256, 1) void attn_tc_kernel(
    const __nv_bfloat16* __restrict__ QRH, const __nv_bfloat16* __restrict__ QRL,
    const __nv_bfloat16* __restrict__ QIH, const __nv_bfloat16* __restrict__ QIL,
    const __nv_bfloat16* __restrict__ KRH, const __nv_bfloat16* __restrict__ KRL,
    const __nv_bfloat16* __restrict__ KIH, const __nv_bfloat16* __restrict__ KIL,
    const __nv_bfloat16* __restrict__ VRH, const __nv_bfloat16* __restrict__ VRL,
    const __nv_bfloat16* __restrict__ VIH, const __nv_bfloat16* __restrict__ VIL,
    float* __restrict__ out_r, float* __restrict__ out_i)
{
    extern __shared__ char smem[];
    const uint32_t sb = smem_u32(smem);
    const int tid = threadIdx.x;
    const int lane = tid & 31;
    const int wid = tid >> 5;
    const int q0 = blockIdx.x * 128;
    const int bh = blockIdx.y;
    const size_t pb = (size_t)bh * Lsz * Dsz;

    const __nv_bfloat16* Qm[4] = {QRH + pb, QRL + pb, QIH + pb, QIL + pb};
    const __nv_bfloat16* Km[8] = {KRH + pb, KRL + pb, KIH + pb, KIL + pb,
                                  VRH + pb, VRL + pb, VIH + pb, VIL + pb};

    // Q tile: 4 mats x 128 rows x 8 chunks = 4096 ops / 256 thr
    #pragma unroll
    for (int mat = 0; mat < 4; ++mat) {
        #pragma unroll
        for (int i = 0; i < 4; ++i) {
            const int op = tid + i * 256;
            const int r = op >> 3, q = op & 7;
            cpa16(sb + mat * AT_QMAT + r * AT_STR + q * 16,
                  Qm[mat] + (size_t)(q0 + r) * Dsz + q * 8);
        }
    }
    CPA_COMMIT();

    auto issue_kv = [&](int kt, int buf) {
        const uint32_t base = sb + AT_QBYTES + buf * AT_STAGE;
        #pragma unroll
        for (int mat = 0; mat < 8; ++mat) {
            #pragma unroll
            for (int i = 0; i < 2; ++i) {
                const int op = tid + i * 256;
                const int r = op >> 3, q = op & 7;
                cpa16(base + mat * AT_MAT + r * AT_STR + q * 16,
                      Km[mat] + (size_t)(kt * 64 + r) * Dsz + q * 8);
            }
        }
        CPA_COMMIT();
    };

    issue_kv(0, 0);
    CPA_WAIT(0);
    __syncthreads();

    float oR[8][4] = {};
    float oI[8][4] = {};
    float mrun0 = -INFINITY, mrun1 = -INFINITY;
    float lrun0 = 0.f, lrun1 = 0.f;
    const float sc = 0.125f * 1.4426950408889634f;

    // fragment address components
    const uint32_t aoff = (uint32_t)((wid * 16 + (lane & 15)) * AT_STR + (lane >> 4) * 16);
    const uint32_t boff = (uint32_t)(((lane & 7) + ((lane >> 4) << 3)) * AT_STR
                                     + ((lane >> 3) & 1) * 16);
    const uint32_t voff = (uint32_t)((lane & 15) * AT_STR + (lane >> 4) * 16);

    for (int kt = 0; kt < NKT; ++kt) {
        if (kt + 1 < NKT) { issue_kv(kt + 1, (kt + 1) & 1); CPA_WAIT(1); }
        else CPA_WAIT(0);
        __syncthreads();
        const uint32_t kb = sb + AT_QBYTES + (kt & 1) * AT_STAGE;

        // ---- scores ----
        float sacc[8][4] = {};
        const int ca[6] = {0, 0, 1, 2, 2, 3};
        const int cb[6] = {0, 1, 0, 2, 3, 2};
        #pragma unroll
        for (int ch = 0; ch < 6; ++ch) {
            const uint32_t qbase = sb + ca[ch] * AT_QMAT + aoff;
            const uint32_t kbase = kb + cb[ch] * AT_MAT + boff;
            #pragma unroll
            for (int ks = 0; ks < 4; ++ks) {
                uint32_t a[4];
                ldsm_x4(a, qbase + ks * 32);
                #pragma unroll
                for (int np = 0; np < 4; ++np) {
                    uint32_t bf[4];
                    ldsm_x4(bf, kbase + np * 16 * AT_STR + ks * 32);
                    mma16816(sacc[2 * np], a, &bf[0]);
                    mma16816(sacc[2 * np + 1], a, &bf[2]);
                }
            }
        }

        // ---- online softmax ----
        float mt0 = -INFINITY, mt1 = -INFINITY;
        #pragma unroll
        for (int j = 0; j < 8; ++j) {
            mt0 = fmaxf(mt0, fmaxf(sacc[j][0], sacc[j][1]));
            mt1 = fmaxf(mt1, fmaxf(sacc[j][2], sacc[j][3]));
        }
        mt0 = fmaxf(mt0, __shfl_xor_sync(0xffffffffu, mt0, 1));
        mt0 = fmaxf(mt0, __shfl_xor_sync(0xffffffffu, mt0, 2));
        mt1 = fmaxf(mt1, __shfl_xor_sync(0xffffffffu, mt1, 1));
        mt1 = fmaxf(mt1, __shfl_xor_sync(0xffffffffu, mt1, 2));
        const float mn0 = fmaxf(mrun0, mt0 * sc);
        const float mn1 = fmaxf(mrun1, mt1 * sc);

        float rs0 = 0.f, rs1 = 0.f;
        uint32_t ph[4][4], pl[4][4];
        #pragma unroll
        for (int j = 0; j < 8; ++j) {
            float p0 = fexp2(fmaf(sacc[j][0], sc, -mn0));
            float p1 = fexp2(fmaf(sacc[j][1], sc, -mn0));
            float p2 = fexp2(fmaf(sacc[j][2], sc, -mn1));
            float p3 = fexp2(fmaf(sacc[j][3], sc, -mn1));
            rs0 += p0 + p1;
            rs1 += p2 + p3;
            __nv_bfloat16 h0, l0, h1, l1, h2, l2, h3, l3;
            split1(p0, h0, l0); split1(p1, h1, l1);
            split1(p2, h2, l2); split1(p3, h3, l3);
            const int ks = j >> 1;
            const int hx = (j & 1) * 2;
            ph[ks][hx + 0] = packbf2(h0, h1);
            ph[ks][hx + 1] = packbf2(h2, h3);
            pl[ks][hx + 0] = packbf2(l0, l1);
            pl[ks][hx + 1] = packbf2(l2, l3);
        }
        // wait: A-frag layout is a0=(r0,k), a1=(r0+8,k), a2=(r0,k+8), a3=(r0+8,k+8).
        // nfrag 2ks -> a0/a1, nfrag 2ks+1 -> a2/a3. Fix ordering:
        //  j even (nfrag 2ks):   ph[ks][0]=pack(p0,p1) (row r0), ph[ks][1]=pack(p2,p3) (row r0+8)
        //  j odd  (nfrag 2ks+1): ph[ks][2], ph[ks][3]
        // (the hx mapping above already does exactly this)

        rs0 += __shfl_xor_sync(0xffffffffu, rs0, 1);
        rs0 += __shfl_xor_sync(0xffffffffu, rs0, 2);
        rs1 += __shfl_xor_sync(0xffffffffu, rs1, 1);
        rs1 += __shfl_xor_sync(0xffffffffu, rs1, 2);
        const float c0 = fexp2(mrun0 - mn0);
        const float c1 = fexp2(mrun1 - mn1);
        lrun0 = lrun0 * c0 + rs0;
        lrun1 = lrun1 * c1 + rs1;
        mrun0 = mn0; mrun1 = mn1;
        #pragma unroll
        for (int j = 0; j < 8; ++j) {
            oR[j][0] *= c0; oR[j][1] *= c0; oR[j][2] *= c1; oR[j][3] *= c1;
            oI[j][0] *= c0; oI[j][1] *= c0; oI[j][2] *= c1; oI[j][3] *= c1;
        }

        // ---- O += P @ V ----
        // chains: (ph,vrh),(ph,vrl),(pl,vrh) -> oR ; (ph,vih),(ph,vil),(pl,vih) -> oI
        const int pvb[6] = {4, 5, 4, 6, 7, 6};
        #pragma unroll
        for (int ch = 0; ch < 6; ++ch) {
            const uint32_t vbase = kb + pvb[ch] * AT_MAT + voff;
            uint32_t (*pp)[4] = (ch == 2 || ch == 5) ? pl : ph;
            float (*oo)[4] = (ch < 3) ? oR : oI;
            #pragma unroll
            for (int ks = 0; ks < 4; ++ks) {
                #pragma unroll
                for (int np = 0; np < 4; ++np) {
                    uint32_t vb[4];
                    ldsm_x4_t(vb, vbase + ks * 16 * AT_STR + np * 32);
                    mma16816(oo[2 * np], pp[ks], &vb[0]);
                    mma16816(oo[2 * np + 1], pp[ks], &vb[2]);
                }
            }
        }
        __syncthreads();
    }

    // finalize
    const float inv0 = 1.0f / lrun0;
    const float inv1 = 1.0f / lrun1;
    const int b = bh >> 4, h = bh & 15;
    const int row0 = q0 + wid * 16 + (lane >> 2);
    const size_t rbase = (size_t)b * Lsz * Esz;
    #pragma unroll
    for (int j = 0; j < 8; ++j) {
        const int col = h * 64 + j * 8 + (lane & 3) * 2;
        float2 v;
        v.x = oR[j][0] * inv0; v.y = oR[j][1] * inv0;
        *(float2*)&out_r[rbase + (size_t)row0 * Esz + col] = v;
        v.x = oR[j][2] * inv1; v.y = oR[j][3] * inv1;
        *(float2*)&out_r[rbase + (size_t)(row0 + 8) * Esz + col] = v;
        v.x = oI[j][0] * inv0; v.y = oI[j][1] * inv0;
        *(float2*)&out_i[rbase + (size_t)row0 * Esz + col] = v;
        v.x = oI[j][2] * inv1; v.y = oI[j][3] * inv1;
        *(float2*)&out_i[rbase + (size_t)(row0 + 8) * Esz + col] = v;
    }
}

// ---------------------------------------------------------------------------
extern "C" void kernel_launch(void* const* d_in, const int* in_sizes, int n_in,
                              void* d_out, int out_size)
{
    (void)in_sizes; (void)n_in; (void)out_size;
    const float* query_r = (const float*)d_in[0];
    const float* query_i = (const float*)d_in[1];
    const float* key_r   = (const float*)d_in[2];
    const float* key_i   = (const float*)d_in[3];
    const float* value_r = (const float*)d_in[4];
    const float* value_i = (const float*)d_in[5];
    const float* Wq_r = (const float*)d_in[6];
    const float* Wq_i = (const float*)d_in[7];
    const float* bq_r = (const float*)d_in[8];
    const float* bq_i = (const float*)d_in[9];
    const float* Wk_r = (const float*)d_in[10];
    const float* Wk_i = (const float*)d_in[11];
    const float* bk_r = (const float*)d_in[12];
    const float* bk_i = (const float*)d_in[13];
    const float* Wv_r = (const float*)d_in[14];
    const float* Wv_i = (const float*)d_in[15];
    const float* bv_r = (const float*)d_in[16];
    const float* bv_i = (const float*)d_in[17];
    const float* Wo_r = (const float*)d_in[18];
    const float* Wo_i = (const float*)d_in[19];
    const float* bo_r = (const float*)d_in[20];
    const float* bo_i = (const float*)d_in[21];

    float* scratch = nullptr;
    cudaGetSymbolAddress((void**)&scratch, g_scratch);
    __nv_bfloat16* acat = nullptr;
    cudaGetSymbolAddress((void**)&acat, g_acat);
    __nv_bfloat16* bcat = nullptr;
    cudaGetSymbolAddress((void**)&bcat, g_bcat);
    __nv_bfloat16* attn = nullptr;
    cudaGetSymbolAddress((void**)&attn, g_attn);

    float* gqr = scratch + 0ull * BLE;
    float* gqi = scratch + 1ull * BLE;
    float* gkr = scratch + 2ull * BLE;
    float* gki = scratch + 3ull * BLE;
    float* gvr = scratch + 4ull * BLE;
    float* gvi = scratch + 5ull * BLE;
    float* gor = scratch + 6ull * BLE;
    float* goi = scratch + 7ull * BLE;

    auto Wc = [&](int s) { return bcat + (size_t)s * Esz * KE; };
    auto At = [&](int s) { return attn + (size_t)s * BHD; };

    splitW_kernel<<<512, 256>>>(Wq_r, Wq_i, Wc(0), Wc(1));
    splitW_kernel<<<512, 256>>>(Wk_r, Wk_i, Wc(2), Wc(3));
    splitW_kernel<<<512, 256>>>(Wv_r, Wv_i, Wc(4), Wc(5));
    splitW_kernel<<<512, 256>>>(Wo_r, Wo_i, Wc(6), Wc(7));

    cudaFuncSetAttribute((const void*)gemm_kernel,
                         cudaFuncAttributeMaxDynamicSharedMemorySize, GEMM_SMEM);
    dim3 gg(Esz / GN, NROW / GM);   // (8, 32)

    splitA_kernel<<<1024, 256>>>(query_r, query_i, acat);
    gemm_kernel<<<gg, 256, GEMM_SMEM>>>(acat, Wc(0), Wc(1), bq_r, bq_i, gqr, gqi);
    splitA_kernel<<<1024, 256>>>(key_r, key_i, acat);
    gemm_kernel<<<gg, 256, GEMM_SMEM>>>(acat, Wc(2), Wc(3), bk_r, bk_i, gkr, gki);
    splitA_kernel<<<1024, 256>>>(value_r, value_i, acat);
    gemm_kernel<<<gg, 256, GEMM_SMEM>>>(acat, Wc(4), Wc(5), bv_r, bv_i, gvr, gvi);

    // attention operand prep (bf16 hi/lo, [BH][L][D])
    attprep_kernel<<<1024, 256>>>(gqr, gqi, At(0), At(1), At(2), At(3));
    attprep_kernel<<<1024, 256>>>(gkr, gki, At(4), At(5), At(6), At(7));
    attprep_kernel<<<1024, 256>>>(gvr, gvi, At(8), At(9), At(10), At(11));

    cudaFuncSetAttribute((const void*)attn_tc_kernel,
                         cudaFuncAttributeMaxDynamicSharedMemorySize, AT_SMEM);
    attn_tc_kernel<<<dim3(Lsz / 128, Bsz * Hsz), 256, AT_SMEM>>>(
        At(0), At(1), At(2), At(3), At(4), At(5), At(6), At(7),
        At(8), At(9), At(10), At(11), gor, goi);

    splitA_kernel<<<1024, 256>>>(gor, goi, acat);
    float* yr = (float*)d_out;
    float* yi = yr + BLE;
    gemm_kernel<<<gg, 256, GEMM_SMEM>>>(acat, Wc(6), Wc(7), bo_r, bo_i, yr, yi);
}